// round 3
// baseline (speedup 1.0000x reference)
#include <cuda_runtime.h>
#include <math.h>

#define BB 4
#define CCH 64
#define HH 128
#define PH 136
#define NPIX (BB*HH*HH)          // 65536
#define NROW (BB*PH*PH)          // 73984
#define NOFF (NPIX*12)           // 786432

// ---------------- scratch (static device allocations) ----------------
__device__ float  g_fp[NROW*CCH];        // padded f, NHWC  (18.9 MB)
__device__ float  g_part[2*NOFF];        // conv partials (2 channel groups)
__device__ float  g_off[NOFF];           // combined offset conv, pixel-major [pix][12]
__device__ float  g_wT[18*64*64];        // weights repacked [slice][c][o]
__device__ double g_sum[12];
__device__ double g_sumsq[12];
__device__ float  g_scale[12];
__device__ float  g_shift[12];

__constant__ int c_used[12] = {1,2,3,5,6,7,10,11,12,14,15,16};

// ---------------- K0: zero stats ----------------
__global__ void k_zero() {
    int t = threadIdx.x;
    if (t < 12) { g_sum[t] = 0.0; g_sumsq[t] = 0.0; }
}

// ---------------- K1: pad + NCHW->NHWC transpose ----------------
// one block per (b, padded row y); smem transpose for coalescing
__global__ void __launch_bounds__(256) k_pad(const float* __restrict__ f) {
    int rb = blockIdx.x;                 // 0 .. B*136-1
    int b = rb / PH, y = rb - b * PH;
    size_t base = (size_t)rb * PH * CCH;
    int tid = threadIdx.x;
    if (y < 4 || y >= 132) {
        for (int idx = tid; idx < PH*CCH; idx += 256) g_fp[base + idx] = 0.f;
        return;
    }
    __shared__ float s[64*137];
    const float* fr = f + ((size_t)b * 64) * 16384 + (size_t)(y - 4) * 128;
    for (int idx = tid; idx < 64*128; idx += 256) {
        int c = idx >> 7, xi = idx & 127;
        s[c*137 + xi] = fr[(size_t)c * 16384 + xi];
    }
    __syncthreads();
    for (int idx = tid; idx < PH*CCH; idx += 256) {
        int x = idx >> 6, c = idx & 63;
        g_fp[base + idx] = (x >= 4 && x < 132) ? s[c*137 + (x - 4)] : 0.f;
    }
}

// ---------------- K2: repack conv weights -> [slice 18][c 64][o 64] ----------------
__global__ void k_wrep(const float* __restrict__ wx, const float* __restrict__ wy) {
    int g = blockIdx.x * 256 + threadIdx.x;       // 18*4096 = 73728
    if (g >= 18*4096) return;
    int s = g >> 12; int r = g & 4095; int c = r >> 6; int o = r & 63;
    g_wT[g] = (s < 9) ? wx[(o*64 + c)*9 + s] : wy[(o*64 + c)*9 + (s - 9)];
}

// ---------------- K3: offset conv (12 used channels, fp32, channel-group partials) ----------------
// grid (4 xtile, 4 ytile, b*2+cgroup); tile 32x32 px, 256 thr, 2x2 px / thread
__global__ void __launch_bounds__(256) k_conv(const float* __restrict__ f,
                                              const float* __restrict__ ow) {
    int bz = blockIdx.z; int b = bz >> 1; int cg = bz & 1;
    int x0 = blockIdx.x * 32, y0 = blockIdx.y * 32;
    __shared__ float s_in[40*41];
    __shared__ float s_w[12*81];
    int tid = threadIdx.x;
    int tx = tid & 15, ty = tid >> 4;
    float acc[12][4];
#pragma unroll
    for (int m = 0; m < 12; m++) { acc[m][0]=acc[m][1]=acc[m][2]=acc[m][3]=0.f; }

    for (int c = cg*32; c < cg*32 + 32; c++) {
        const float* fc = f + (size_t)(b*64 + c) * 16384;
        for (int idx = tid; idx < 1600; idx += 256) {
            int r = idx / 40, col = idx - r*40;
            int gy = y0 - 4 + r, gx = x0 - 4 + col;
            s_in[r*41 + col] = (gy >= 0 && gy < 128 && gx >= 0 && gx < 128)
                               ? fc[gy*128 + gx] : 0.f;
        }
        for (int idx = tid; idx < 972; idx += 256) {
            int m = idx / 81, t = idx - m*81;
            s_w[idx] = ow[(size_t)(c_used[m]*64 + c) * 81 + t];
        }
        __syncthreads();
        int ry = 2*ty, rx = 2*tx;
        for (int ky = 0; ky < 9; ky++) {
#pragma unroll
            for (int kx = 0; kx < 9; kx++) {
                float i00 = s_in[(ry+ky)*41 + rx + kx];
                float i01 = s_in[(ry+ky)*41 + rx + kx + 1];
                float i10 = s_in[(ry+ky+1)*41 + rx + kx];
                float i11 = s_in[(ry+ky+1)*41 + rx + kx + 1];
                int t = ky*9 + kx;
#pragma unroll
                for (int m = 0; m < 12; m++) {
                    float w = s_w[m*81 + t];
                    acc[m][0] += w * i00; acc[m][1] += w * i01;
                    acc[m][2] += w * i10; acc[m][3] += w * i11;
                }
            }
        }
        __syncthreads();
    }
    float* dst = g_part + (size_t)cg * NOFF;
#pragma unroll
    for (int dy = 0; dy < 2; dy++)
#pragma unroll
    for (int dx = 0; dx < 2; dx++) {
        int pix = (b*128 + y0 + 2*ty + dy) * 128 + x0 + 2*tx + dx;
        int q = dy*2 + dx;
#pragma unroll
        for (int m = 0; m < 12; m++) dst[(size_t)pix*12 + m] = acc[m][q];
    }
}

// ---------------- K4: combine partials + fp64 stats ----------------
__global__ void __launch_bounds__(256) k_comb() {
    int pix = blockIdx.x * 256 + threadIdx.x;     // 256 blocks
    float v[12];
#pragma unroll
    for (int m = 0; m < 12; m++) {
        float a = g_part[(size_t)pix*12 + m] + g_part[NOFF + (size_t)pix*12 + m];
        v[m] = a;
        g_off[(size_t)pix*12 + m] = a;
    }
    __shared__ double ss[8][12], sq[8][12];
    int lane = threadIdx.x & 31, w = threadIdx.x >> 5;
#pragma unroll
    for (int m = 0; m < 12; m++) {
        double dv = (double)v[m];
        double dq = (double)v[m] * (double)v[m];
        for (int o = 16; o > 0; o >>= 1) {
            dv += __shfl_down_sync(0xffffffff, dv, o);
            dq += __shfl_down_sync(0xffffffff, dq, o);
        }
        if (lane == 0) { ss[w][m] = dv; sq[w][m] = dq; }
    }
    __syncthreads();
    if (threadIdx.x < 12) {
        double a = 0, q = 0;
        for (int w2 = 0; w2 < 8; w2++) { a += ss[w2][threadIdx.x]; q += sq[w2][threadIdx.x]; }
        atomicAdd(&g_sum[threadIdx.x], a);
        atomicAdd(&g_sumsq[threadIdx.x], q);
    }
}

// ---------------- K5: BN finalize (scale/shift per used channel) ----------------
__global__ void k_final(const float* __restrict__ gamma, const float* __restrict__ beta) {
    int t = threadIdx.x;
    if (t >= 12) return;
    double mean = g_sum[t] / 65536.0;
    double var  = g_sumsq[t] / 65536.0 - mean * mean;
    double sc   = (double)gamma[c_used[t]] / sqrt(var + 1e-5);
    g_scale[t] = (float)sc;
    g_shift[t] = (float)((double)beta[c_used[t]] - mean * sc);
}

// ---------------- K6: main fused gather + GEMM ----------------
// block = 64 pixels (one b, one row i, half-row jt) x 64 outputs
// grid (2 jt, 128 i, 4 b) = 1024 blocks, 256 threads, 4o x 4px register tile
__global__ void __launch_bounds__(256) k_main(const float* __restrict__ bx,
                                              const float* __restrict__ by,
                                              float* __restrict__ out) {
    __shared__ int   s_idx[18][64];
    __shared__ float sW[4096];   // [c][o] for current slice
    __shared__ float sV[4096];   // [c][p] gathered values
    int tid = threadIdx.x;
    int b = blockIdx.z, i = blockIdx.y, jt = blockIdx.x;

    if (tid < 64) {
        int j = jt*64 + tid;
        const float* op = g_off + (size_t)(((b*128 + i)*128 + j)) * 12;
        float t[12];
#pragma unroll
        for (int m = 0; m < 12; m++) t[m] = tanhf(op[m] * g_scale[m] + g_shift[m]);
        float cz[9], cw[9];
        cz[0] = 0.f; cz[1] = t[0]; cz[2] = t[0] + t[1]; cz[3] = cz[2] + t[2];
        cz[7] = t[5]; cz[6] = t[5] + t[4]; cz[5] = cz[6] + t[3];
        cz[4] = (cz[3] + cz[5]) * 0.5f; cz[8] = 0.f;
        cw[0] = 0.f; cw[1] = t[6]; cw[2] = t[6] + t[7]; cw[3] = cw[2] + t[8];
        cw[7] = t[11]; cw[6] = t[11] + t[10]; cw[5] = cw[6] + t[9];
        cw[4] = (cw[3] + cw[5]) * 0.5f; cw[8] = 0.f;
#pragma unroll
        for (int k = 0; k < 9; k++) {
            // replicate reference fp32 association: (int const) + cum, then floor
            float y2 = (float)(i + 8 - k) + cz[k];
            float x2 = (float)(j + k)     + cz[k];
            int idx2 = b*16384 + (int)floorf(y2) * 136 + (int)floorf(x2);
            if (idx2 < 0) idx2 += NROW;
            idx2 = idx2 < 0 ? 0 : (idx2 > NROW-1 ? NROW-1 : idx2);
            s_idx[k][tid] = idx2;

            float y3 = (float)(i + k) + cw[k];
            float x3 = (float)(j + k) - cw[k];
            int idx3 = b*16384 + (int)floorf(y3) * 136 + (int)floorf(x3);
            if (idx3 < 0) idx3 += NROW;
            idx3 = idx3 < 0 ? 0 : (idx3 > NROW-1 ? NROW-1 : idx3);
            s_idx[9 + k][tid] = idx3;
        }
    }

    float4 acc[4];
#pragma unroll
    for (int oi = 0; oi < 4; oi++) acc[oi] = make_float4(0.f, 0.f, 0.f, 0.f);
    int txp = tid & 15, tyo = tid >> 4;
    __syncthreads();

    for (int s = 0; s < 18; s++) {
        // stage weights [c][o]
        const float4* wsrc = (const float4*)(g_wT + (size_t)s * 4096);
#pragma unroll
        for (int u = 0; u < 4; u++)
            ((float4*)sW)[tid + u*256] = wsrc[tid + u*256];
        // gather V: thread (p = tid&63, cq = tid>>6) copies 16 channels of pixel p
        int p = tid & 63, cq = tid >> 6;
        const float4* vsrc = (const float4*)(g_fp + (size_t)s_idx[s][p] * 64 + cq * 16);
#pragma unroll
        for (int u = 0; u < 4; u++) {
            float4 vv = vsrc[u];
            int cb = cq*16 + u*4;
            sV[(cb+0)*64 + p] = vv.x;
            sV[(cb+1)*64 + p] = vv.y;
            sV[(cb+2)*64 + p] = vv.z;
            sV[(cb+3)*64 + p] = vv.w;
        }
        __syncthreads();
#pragma unroll 8
        for (int cc = 0; cc < 64; cc++) {
            float4 a = *(const float4*)&sW[cc*64 + tyo*4];
            float4 v = *(const float4*)&sV[cc*64 + txp*4];
            acc[0].x += a.x*v.x; acc[0].y += a.x*v.y; acc[0].z += a.x*v.z; acc[0].w += a.x*v.w;
            acc[1].x += a.y*v.x; acc[1].y += a.y*v.y; acc[1].z += a.y*v.z; acc[1].w += a.y*v.w;
            acc[2].x += a.z*v.x; acc[2].y += a.z*v.y; acc[2].z += a.z*v.z; acc[2].w += a.z*v.w;
            acc[3].x += a.w*v.x; acc[3].y += a.w*v.y; acc[3].z += a.w*v.z; acc[3].w += a.w*v.w;
        }
        __syncthreads();
    }

#pragma unroll
    for (int oi = 0; oi < 4; oi++) {
        int o = tyo*4 + oi;
        float bias = bx[o] + by[o];
        float4 r = acc[oi];
        r.x += bias; r.y += bias; r.z += bias; r.w += bias;
        *(float4*)&out[((size_t)(b*64 + o) * 128 + i) * 128 + jt*64 + txp*4] = r;
    }
}

// ---------------- launch ----------------
extern "C" void kernel_launch(void* const* d_in, const int* in_sizes, int n_in,
                              void* d_out, int out_size) {
    const float* f     = (const float*)d_in[0];
    const float* ow    = (const float*)d_in[1];
    // d_in[2] offset_b: cancels exactly inside BatchNorm -> unused
    const float* gamma = (const float*)d_in[3];
    const float* beta  = (const float*)d_in[4];
    const float* wx    = (const float*)d_in[5];
    const float* bx    = (const float*)d_in[6];
    const float* wy    = (const float*)d_in[7];
    const float* by    = (const float*)d_in[8];
    float* out = (float*)d_out;

    k_zero<<<1, 32>>>();
    k_pad<<<BB*PH, 256>>>(f);
    k_wrep<<<288, 256>>>(wx, wy);
    k_conv<<<dim3(4, 4, 8), 256>>>(f, ow);
    k_comb<<<256, 256>>>();
    k_final<<<1, 32>>>(gamma, beta);
    k_main<<<dim3(2, 128, 4), 256>>>(bx, by, out);
}